// round 3
// baseline (speedup 1.0000x reference)
#include <cuda_runtime.h>
#include <cuda_bf16.h>

// Problem constants (fixed by the reference module)
#define BB   8
#define KK   16
#define MH   28
#define MW   28
#define IMG  512

#define THREADS 256
#define ROW_STRIPS 8                      // blocks per (b,k) along y
#define ROWS_PER_BLOCK (IMG / ROW_STRIPS) // 64
// float4s per block = 64*512/4 = 8192 ; per thread = 8192/256 = 32
#define ITERS ((ROWS_PER_BLOCK * IMG) / (4 * THREADS))

__global__ __launch_bounds__(THREADS, 8)
void wholemask_kernel(const float* __restrict__ bbox,    // (B,K,4)
                      const int*   __restrict__ counts,  // (B,1)
                      const float* __restrict__ masks,   // (B,K,1,28,28)
                      float*       __restrict__ out)     // (B,K,1,512,512)
{
    __shared__ float s_mask[MH * MW];
    __shared__ int   s_sx[IMG];   // sample col index, or -1 if outside/invalid
    __shared__ int   s_sy[IMG];   // sample row index, or -1 if outside/invalid

    const int bk  = blockIdx.y;           // b*K + k
    const int b   = bk >> 4;              // K = 16
    const int k   = bk & 15;
    const int tid = threadIdx.x;

    // ---- bbox decode (all threads redundantly; cheap, avoids a sync) ----
    const float4 bbf = __ldg((const float4*)(bbox + bk * 4));
    // jnp.round = round-half-to-even == __float2int_rn
    int y1 = min(max(__float2int_rn(bbf.x), 0), IMG - 1);
    int x1 = min(max(__float2int_rn(bbf.y), 0), IMG - 1);
    int y2 = min(max(__float2int_rn(bbf.z), y1 + 1), IMG);
    int x2 = min(max(__float2int_rn(bbf.w), x1 + 1), IMG);
    const int h = y2 - y1;
    const int w = x2 - x1;
    const bool valid = (k < __ldg(counts + b));

    // ---- build LUTs + stage mask in shared ----
    for (int x = tid; x < IMG; x += THREADS) {
        int rx = x - x1;
        int ry = x - y1;
        // operands non-negative where used: C '/' == Python '//'
        s_sx[x] = (valid && x >= x1 && x < x2) ? min((rx * MW) / w, MW - 1) : -1;
        s_sy[x] = (valid && x >= y1 && x < y2) ? min((ry * MH) / h, MH - 1) : -1;
    }
    for (int i = tid; i < MH * MW; i += THREADS)
        s_mask[i] = __ldg(masks + (size_t)bk * MH * MW + i);
    __syncthreads();

    // ---- main write loop: one float4 per iteration per thread ----
    const int row0 = blockIdx.x * ROWS_PER_BLOCK;
    float* __restrict__ outp = out + (size_t)bk * IMG * IMG;

#pragma unroll 4
    for (int i = 0; i < ITERS; i++) {
        const int lin = i * THREADS + tid;      // float4 index within strip
        const int row = row0 + (lin >> 7);      // 128 float4 per row
        const int x4  = (lin & 127) << 2;

        float4 v = make_float4(0.f, 0.f, 0.f, 0.f);
        const int sy = s_sy[row];               // warp-uniform (warp = 1/4 row)
        if (sy >= 0) {
            const float* mrow = s_mask + sy * MW;
            const int4 sx = *(const int4*)(s_sx + x4);   // x4 % 4 == 0: aligned
            if (sx.x >= 0) v.x = mrow[sx.x];
            if (sx.y >= 0) v.y = mrow[sx.y];
            if (sx.z >= 0) v.z = mrow[sx.z];
            if (sx.w >= 0) v.w = mrow[sx.w];
        }
        // Output is write-once, never re-read: streaming (evict-first) store.
        __stcs((float4*)(outp + (size_t)row * IMG + x4), v);
    }
}

extern "C" void kernel_launch(void* const* d_in, const int* in_sizes, int n_in,
                              void* d_out, int out_size)
{
    const float* bbox   = (const float*)d_in[0];  // (8,16,4)  f32
    const int*   counts = (const int*)  d_in[1];  // (8,1)     i32
    const float* masks  = (const float*)d_in[2];  // (8,16,1,28,28) f32
    // d_in[3], d_in[4] = img_h, img_w (compile-time 512 here)
    float* out = (float*)d_out;                   // (8,16,1,512,512) f32

    dim3 grid(ROW_STRIPS, BB * KK);               // (8, 128) = 1024 blocks
    wholemask_kernel<<<grid, THREADS>>>(bbox, counts, masks, out);
}

// round 16
// speedup vs baseline: 1.2520x; 1.2520x over previous
#include <cuda_runtime.h>
#include <cuda_bf16.h>

// Problem constants (fixed by the reference module)
#define BB   8
#define KK   16
#define MH   28
#define MW   28
#define IMG  512

#define THREADS 256
#define ROW_STRIPS 8                      // blocks per (b,k) along y
#define ROWS_PER_BLOCK (IMG / ROW_STRIPS) // 64
#define ROWS_PER_THREAD 32                // 2 thread-halves cover 64 rows

__global__ __launch_bounds__(THREADS, 8)
void wholemask_kernel(const float* __restrict__ bbox,    // (B,K,4)
                      const int*   __restrict__ counts,  // (B,1)
                      const float* __restrict__ masks,   // (B,K,1,28,28)
                      float*       __restrict__ out)     // (B,K,1,512,512)
{
    __shared__ float s_mask[MH * MW];
    __shared__ int   s_sx[IMG];   // sample col index, or -1 if outside/invalid
    __shared__ int   s_sy[IMG];   // sample row index, or -1 if outside/invalid

    const int bk  = blockIdx.y;           // b*K + k
    const int b   = bk >> 4;              // K = 16
    const int k   = bk & 15;
    const int tid = threadIdx.x;

    // ---- bbox decode (all threads redundantly; cheap, avoids a sync) ----
    const float4 bbf = __ldg((const float4*)(bbox + bk * 4));
    // jnp.round = round-half-to-even == __float2int_rn
    int y1 = min(max(__float2int_rn(bbf.x), 0), IMG - 1);
    int x1 = min(max(__float2int_rn(bbf.y), 0), IMG - 1);
    int y2 = min(max(__float2int_rn(bbf.z), y1 + 1), IMG);
    int x2 = min(max(__float2int_rn(bbf.w), x1 + 1), IMG);
    const int h = y2 - y1;
    const int w = x2 - x1;
    const bool valid = (k < __ldg(counts + b));

    // ---- build LUTs + stage mask in shared (once per block) ----
    for (int x = tid; x < IMG; x += THREADS) {
        int rx = x - x1;
        int ry = x - y1;
        // operands non-negative where used: C '/' == Python '//'
        s_sx[x] = (valid && x >= x1 && x < x2) ? min((rx * MW) / w, MW - 1) : -1;
        s_sy[x] = (valid && x >= y1 && x < y2) ? min((ry * MH) / h, MH - 1) : -1;
    }
    for (int i = tid; i < MH * MW; i += THREADS)
        s_mask[i] = __ldg(masks + (size_t)bk * MH * MW + i);
    __syncthreads();

    // ---- column-stationary main loop ----
    // Thread owns one float4 column for 32 consecutive rows.
    // Warp lanes = adjacent columns, same row -> 512B coalesced stores,
    // warp-uniform s_sy[row] lookups.
    const int c4    = tid & 127;                       // float4 column 0..127
    const int half  = tid >> 7;                        // 0 or 1
    const int rbase = blockIdx.x * ROWS_PER_BLOCK + half * ROWS_PER_THREAD;
    const int x4    = c4 << 2;

    float* p = out + (size_t)bk * IMG * IMG + (size_t)rbase * IMG + x4;
    const float4 zero = make_float4(0.f, 0.f, 0.f, 0.f);

    // Loop-invariant column sample indices (one aligned LDS.128 per thread).
    const int4 sx = *(const int4*)(s_sx + x4);

    if (sx.x < 0 && sx.y < 0 && sx.z < 0 && sx.w < 0) {
        // Column never intersects the box (or invalid k): pure store loop.
        // ~2 instructions per float4 (STG.128 + IADD), fully unrolled.
#pragma unroll
        for (int r = 0; r < ROWS_PER_THREAD; r++) {
            __stcs((float4*)p, zero);
            p += IMG;
        }
    } else {
        // Active column: per row one warp-uniform LDS + <=4 predicated
        // mask gathers (predicates are loop-invariant).
#pragma unroll 8
        for (int r = 0; r < ROWS_PER_THREAD; r++) {
            float4 v = zero;
            const int sy = s_sy[rbase + r];            // warp-uniform
            if (sy >= 0) {
                const float* mrow = s_mask + sy * MW;
                if (sx.x >= 0) v.x = mrow[sx.x];
                if (sx.y >= 0) v.y = mrow[sx.y];
                if (sx.z >= 0) v.z = mrow[sx.z];
                if (sx.w >= 0) v.w = mrow[sx.w];
            }
            __stcs((float4*)p, v);
            p += IMG;
        }
    }
}

extern "C" void kernel_launch(void* const* d_in, const int* in_sizes, int n_in,
                              void* d_out, int out_size)
{
    const float* bbox   = (const float*)d_in[0];  // (8,16,4)  f32
    const int*   counts = (const int*)  d_in[1];  // (8,1)     i32
    const float* masks  = (const float*)d_in[2];  // (8,16,1,28,28) f32
    // d_in[3], d_in[4] = img_h, img_w (compile-time 512 here)
    float* out = (float*)d_out;                   // (8,16,1,512,512) f32

    dim3 grid(ROW_STRIPS, BB * KK);               // (8, 128) = 1024 blocks
    wholemask_kernel<<<grid, THREADS>>>(bbox, counts, masks, out);
}